// round 7
// baseline (speedup 1.0000x reference)
#include <cuda_runtime.h>
#include <math.h>

#define LAMBDA 1.5f
#define B_SZ 32
#define N_SZ 2048
#define HID 256
#define THREADS 256
#define WARPS_PER_BLOCK 8
#define TILES 4                      // row-groups per block (x staged once)
#define ROWS_PER_BLOCK (WARPS_PER_BLOCK * TILES)

// ---------------------------------------------------------------------------
// Fully fused, row-tiled: each block stages x once and processes 4 row-groups
// (32 rows) of the same batch. |x|^2 accumulated in-loop on the first tile
// only. 2048 blocks -> ~3 waves instead of ~11, 4x less x-staging traffic.
// ---------------------------------------------------------------------------
__global__ __launch_bounds__(THREADS, 6) void fused_kernel(
    const float* __restrict__ Yr, const float* __restrict__ Yi,
    const float* __restrict__ xr, const float* __restrict__ xi,
    const float* __restrict__ xpr, const float* __restrict__ xpi,
    const float* __restrict__ d3w, const float* __restrict__ d3b,
    const float* __restrict__ w1, const float* __restrict__ b1,
    const float* __restrict__ w2, const float* __restrict__ b2,
    float* __restrict__ out) {

    __shared__ float sxr[N_SZ];
    __shared__ float sxi[N_SZ];
    __shared__ float sw1[HID];
    __shared__ float sb1[HID];
    __shared__ float sw2[HID];

    const int tid = threadIdx.x;
    const int b = blockIdx.y;

    // ---- Stage x vectors for this batch + MLP weights into shared (once) --
    {
        const float4* xr4 = (const float4*)(xr + (size_t)b * N_SZ);
        const float4* xi4 = (const float4*)(xi + (size_t)b * N_SZ);
        float4* sxr4 = (float4*)sxr;
        float4* sxi4 = (float4*)sxi;
        #pragma unroll
        for (int k = tid; k < N_SZ / 4; k += THREADS) {
            sxr4[k] = xr4[k];
            sxi4[k] = xi4[k];
        }
        if (tid < HID) {
            sw1[tid] = w1[tid];
            sb1[tid] = b1[tid];
            sw2[tid] = w2[tid];
        }
    }
    __syncthreads();

    const int wid = tid >> 5;
    const int lid = tid & 31;
    const float4* sxr4 = (const float4*)sxr;
    const float4* sxi4 = (const float4*)sxi;

    const float dw = d3w[0];
    const float db = d3b[0];
    const float b2v = b2[0];

    float sc = 0.f;   // per-batch scale, computed on tile 0, reused after

    #pragma unroll
    for (int t = 0; t < TILES; t++) {
        const int n = blockIdx.x * ROWS_PER_BLOCK + t * WARPS_PER_BLOCK + wid;

        const size_t row_base = (((size_t)b * N_SZ) + n) * N_SZ;
        const float4* yr4 = (const float4*)(Yr + row_base);
        const float4* yi4 = (const float4*)(Yi + row_base);

        float rr = 0.f, ii = 0.f, ri = 0.f, ir = 0.f, ss = 0.f;

        #pragma unroll 4
        for (int k = lid; k < N_SZ / 4; k += 32) {
            float4 a = yr4[k];
            float4 c = yi4[k];
            float4 u = sxr4[k];
            float4 v = sxi4[k];
            rr = fmaf(a.x, u.x, rr); rr = fmaf(a.y, u.y, rr);
            rr = fmaf(a.z, u.z, rr); rr = fmaf(a.w, u.w, rr);
            ii = fmaf(c.x, v.x, ii); ii = fmaf(c.y, v.y, ii);
            ii = fmaf(c.z, v.z, ii); ii = fmaf(c.w, v.w, ii);
            ri = fmaf(a.x, v.x, ri); ri = fmaf(a.y, v.y, ri);
            ri = fmaf(a.z, v.z, ri); ri = fmaf(a.w, v.w, ri);
            ir = fmaf(c.x, u.x, ir); ir = fmaf(c.y, u.y, ir);
            ir = fmaf(c.z, u.z, ir); ir = fmaf(c.w, u.w, ir);
            if (t == 0) {  // compile-time specialized: |x|^2 on first tile only
                ss = fmaf(u.x, u.x, ss); ss = fmaf(u.y, u.y, ss);
                ss = fmaf(u.z, u.z, ss); ss = fmaf(u.w, u.w, ss);
                ss = fmaf(v.x, v.x, ss); ss = fmaf(v.y, v.y, ss);
                ss = fmaf(v.z, v.z, ss); ss = fmaf(v.w, v.w, ss);
            }
        }

        #pragma unroll
        for (int off = 16; off > 0; off >>= 1) {
            rr += __shfl_xor_sync(0xFFFFFFFFu, rr, off);
            ii += __shfl_xor_sync(0xFFFFFFFFu, ii, off);
            ri += __shfl_xor_sync(0xFFFFFFFFu, ri, off);
            ir += __shfl_xor_sync(0xFFFFFFFFu, ir, off);
            if (t == 0)
                ss += __shfl_xor_sync(0xFFFFFFFFu, ss, off);
        }
        if (t == 0)
            sc = -(LAMBDA * LAMBDA) * (1.0f - ss / (float)N_SZ);

        // ---- Epilogue for this row ----
        const size_t idx = (size_t)b * N_SZ + n;

        float x1r = fmaf(LAMBDA * (rr - ii), dw, db);
        float x1i = fmaf(LAMBDA * (ri + ir), dw, db);
        x1r = fmaf(sc, xpr[idx], x1r);
        x1i = fmaf(sc, xpi[idx], x1i);

        const float xabs = sqrtf(x1r * x1r + x1i * x1i);

        float partial = 0.f;
        #pragma unroll
        for (int j = lid; j < HID; j += 32) {
            float h = fmaxf(fmaf(xabs, sw1[j], sb1[j]), 0.f);
            partial = fmaf(h, sw2[j], partial);
        }
        #pragma unroll
        for (int off = 16; off > 0; off >>= 1)
            partial += __shfl_xor_sync(0xFFFFFFFFu, partial, off);

        if (lid == 0) {
            float g = tanhf(partial + b2v);
            float q = g / fmaxf(xabs, 1e-12f);
            out[idx] = x1r * q;                          // real part
            out[(size_t)B_SZ * N_SZ + idx] = x1i * q;    // imag part
        }
    }
}

extern "C" void kernel_launch(void* const* d_in, const int* in_sizes, int n_in,
                              void* d_out, int out_size) {
    const float* Yr  = (const float*)d_in[0];
    const float* Yi  = (const float*)d_in[1];
    const float* xr  = (const float*)d_in[2];
    const float* xi  = (const float*)d_in[3];
    const float* xpr = (const float*)d_in[4];
    const float* xpi = (const float*)d_in[5];
    const float* d3w = (const float*)d_in[6];
    const float* d3b = (const float*)d_in[7];
    const float* w1  = (const float*)d_in[8];
    const float* b1  = (const float*)d_in[9];
    const float* w2  = (const float*)d_in[10];
    const float* b2  = (const float*)d_in[11];
    float* out = (float*)d_out;

    dim3 grid(N_SZ / ROWS_PER_BLOCK, B_SZ);
    fused_kernel<<<grid, THREADS>>>(Yr, Yi, xr, xi, xpr, xpi,
                                    d3w, d3b, w1, b1, w2, b2, out);
}

// round 8
// speedup vs baseline: 1.3541x; 1.3541x over previous
#include <cuda_runtime.h>
#include <math.h>

#define LAMBDA 1.5f
#define B_SZ 32
#define N_SZ 2048
#define HID 256
#define THREADS 256
#define WARPS_PER_BLOCK 8   // one output row per warp

// ---------------------------------------------------------------------------
// R6 structure (best: 160.2us, DRAM 84.1%) with inner unroll 4 -> 8 to double
// in-flight LDG.128 per warp (MLP_p1 8 -> 16). Everything else unchanged:
// 256 thr / 8 warps / 1 row per warp, |x|^2 fused into the streaming loop,
// no prologue kernel, plain LDG (no .cs), launch_bounds(256,6) pins regs<=41.
// ---------------------------------------------------------------------------
__global__ __launch_bounds__(THREADS, 6) void fused_kernel(
    const float* __restrict__ Yr, const float* __restrict__ Yi,
    const float* __restrict__ xr, const float* __restrict__ xi,
    const float* __restrict__ xpr, const float* __restrict__ xpi,
    const float* __restrict__ d3w, const float* __restrict__ d3b,
    const float* __restrict__ w1, const float* __restrict__ b1,
    const float* __restrict__ w2, const float* __restrict__ b2,
    float* __restrict__ out) {

    __shared__ float sxr[N_SZ];
    __shared__ float sxi[N_SZ];
    __shared__ float sw1[HID];
    __shared__ float sb1[HID];
    __shared__ float sw2[HID];

    const int tid = threadIdx.x;
    const int b = blockIdx.y;

    // ---- Stage x vectors for this batch + MLP weights into shared ----
    {
        const float4* xr4 = (const float4*)(xr + (size_t)b * N_SZ);
        const float4* xi4 = (const float4*)(xi + (size_t)b * N_SZ);
        float4* sxr4 = (float4*)sxr;
        float4* sxi4 = (float4*)sxi;
        #pragma unroll
        for (int k = tid; k < N_SZ / 4; k += THREADS) {
            sxr4[k] = xr4[k];
            sxi4[k] = xi4[k];
        }
        if (tid < HID) {
            sw1[tid] = w1[tid];
            sb1[tid] = b1[tid];
            sw2[tid] = w2[tid];
        }
    }
    __syncthreads();

    const int wid = tid >> 5;
    const int lid = tid & 31;
    const int n = blockIdx.x * WARPS_PER_BLOCK + wid;

    const size_t row_base = (((size_t)b * N_SZ) + n) * N_SZ;
    const float4* yr4 = (const float4*)(Yr + row_base);
    const float4* yi4 = (const float4*)(Yi + row_base);
    const float4* sxr4 = (const float4*)sxr;
    const float4* sxi4 = (const float4*)sxi;

    // ---- Main streaming loop: 4 dot products + |x|^2 sum, all fused ----
    float rr = 0.f, ii = 0.f, ri = 0.f, ir = 0.f, ss = 0.f;

    #pragma unroll 8
    for (int k = lid; k < N_SZ / 4; k += 32) {
        float4 a = yr4[k];
        float4 c = yi4[k];
        float4 u = sxr4[k];
        float4 v = sxi4[k];
        rr = fmaf(a.x, u.x, rr); rr = fmaf(a.y, u.y, rr);
        rr = fmaf(a.z, u.z, rr); rr = fmaf(a.w, u.w, rr);
        ii = fmaf(c.x, v.x, ii); ii = fmaf(c.y, v.y, ii);
        ii = fmaf(c.z, v.z, ii); ii = fmaf(c.w, v.w, ii);
        ri = fmaf(a.x, v.x, ri); ri = fmaf(a.y, v.y, ri);
        ri = fmaf(a.z, v.z, ri); ri = fmaf(a.w, v.w, ri);
        ir = fmaf(c.x, u.x, ir); ir = fmaf(c.y, u.y, ir);
        ir = fmaf(c.z, u.z, ir); ir = fmaf(c.w, u.w, ir);
        ss = fmaf(u.x, u.x, ss); ss = fmaf(u.y, u.y, ss);
        ss = fmaf(u.z, u.z, ss); ss = fmaf(u.w, u.w, ss);
        ss = fmaf(v.x, v.x, ss); ss = fmaf(v.y, v.y, ss);
        ss = fmaf(v.z, v.z, ss); ss = fmaf(v.w, v.w, ss);
    }

    // butterfly reduce all five accumulators -> every lane has full sums
    #pragma unroll
    for (int off = 16; off > 0; off >>= 1) {
        rr += __shfl_xor_sync(0xFFFFFFFFu, rr, off);
        ii += __shfl_xor_sync(0xFFFFFFFFu, ii, off);
        ri += __shfl_xor_sync(0xFFFFFFFFu, ri, off);
        ir += __shfl_xor_sync(0xFFFFFFFFu, ir, off);
        ss += __shfl_xor_sync(0xFFFFFFFFu, ss, off);
    }

    // ---- Epilogue (per-warp; no cross-warp communication needed) ----
    const float dw = d3w[0];
    const float db = d3b[0];
    const float sc = -(LAMBDA * LAMBDA) * (1.0f - ss / (float)N_SZ);
    const size_t idx = (size_t)b * N_SZ + n;

    float x1r = fmaf(LAMBDA * (rr - ii), dw, db);
    float x1i = fmaf(LAMBDA * (ri + ir), dw, db);
    x1r = fmaf(sc, xpr[idx], x1r);
    x1i = fmaf(sc, xpi[idx], x1i);

    const float xabs = sqrtf(x1r * x1r + x1i * x1i);

    // MLP: 256 hidden units, 8 per lane
    float partial = 0.f;
    #pragma unroll
    for (int j = lid; j < HID; j += 32) {
        float h = fmaxf(fmaf(xabs, sw1[j], sb1[j]), 0.f);
        partial = fmaf(h, sw2[j], partial);
    }
    #pragma unroll
    for (int off = 16; off > 0; off >>= 1)
        partial += __shfl_xor_sync(0xFFFFFFFFu, partial, off);

    if (lid == 0) {
        float g = tanhf(partial + b2[0]);
        float q = g / fmaxf(xabs, 1e-12f);
        out[idx] = x1r * q;                          // real part
        out[(size_t)B_SZ * N_SZ + idx] = x1i * q;    // imag part
    }
}

extern "C" void kernel_launch(void* const* d_in, const int* in_sizes, int n_in,
                              void* d_out, int out_size) {
    const float* Yr  = (const float*)d_in[0];
    const float* Yi  = (const float*)d_in[1];
    const float* xr  = (const float*)d_in[2];
    const float* xi  = (const float*)d_in[3];
    const float* xpr = (const float*)d_in[4];
    const float* xpi = (const float*)d_in[5];
    const float* d3w = (const float*)d_in[6];
    const float* d3b = (const float*)d_in[7];
    const float* w1  = (const float*)d_in[8];
    const float* b1  = (const float*)d_in[9];
    const float* w2  = (const float*)d_in[10];
    const float* b2  = (const float*)d_in[11];
    float* out = (float*)d_out;

    dim3 grid(N_SZ / WARPS_PER_BLOCK, B_SZ);
    fused_kernel<<<grid, THREADS>>>(Yr, Yi, xr, xi, xpr, xpi,
                                    d3w, d3b, w1, b1, w2, b2, out);
}

// round 9
// speedup vs baseline: 1.3724x; 1.0135x over previous
#include <cuda_runtime.h>
#include <math.h>

#define LAMBDA 1.5f
#define B_SZ 32
#define N_SZ 2048
#define HID 256
#define THREADS 256
#define WARPS_PER_BLOCK 8   // one output row per warp

// ---------------------------------------------------------------------------
// R8 structure (156.2us, DRAM 86.5%) with the 16-iteration k-loop FULLY
// unrolled (unroll 8 -> 16): zero loop overhead, whole load DAG visible to
// ptxas for max in-flight LDG.128 under the 41-reg budget. Scalar epilogue
// params hoisted above the loop so their latency is covered by the stream.
// ---------------------------------------------------------------------------
__global__ __launch_bounds__(THREADS, 6) void fused_kernel(
    const float* __restrict__ Yr, const float* __restrict__ Yi,
    const float* __restrict__ xr, const float* __restrict__ xi,
    const float* __restrict__ xpr, const float* __restrict__ xpi,
    const float* __restrict__ d3w, const float* __restrict__ d3b,
    const float* __restrict__ w1, const float* __restrict__ b1,
    const float* __restrict__ w2, const float* __restrict__ b2,
    float* __restrict__ out) {

    __shared__ float sxr[N_SZ];
    __shared__ float sxi[N_SZ];
    __shared__ float sw1[HID];
    __shared__ float sb1[HID];
    __shared__ float sw2[HID];

    const int tid = threadIdx.x;
    const int b = blockIdx.y;

    // ---- Stage x vectors for this batch + MLP weights into shared ----
    {
        const float4* xr4 = (const float4*)(xr + (size_t)b * N_SZ);
        const float4* xi4 = (const float4*)(xi + (size_t)b * N_SZ);
        float4* sxr4 = (float4*)sxr;
        float4* sxi4 = (float4*)sxi;
        #pragma unroll
        for (int k = tid; k < N_SZ / 4; k += THREADS) {
            sxr4[k] = xr4[k];
            sxi4[k] = xi4[k];
        }
        if (tid < HID) {
            sw1[tid] = w1[tid];
            sb1[tid] = b1[tid];
            sw2[tid] = w2[tid];
        }
    }
    __syncthreads();

    const int wid = tid >> 5;
    const int lid = tid & 31;
    const int n = blockIdx.x * WARPS_PER_BLOCK + wid;

    const size_t row_base = (((size_t)b * N_SZ) + n) * N_SZ;
    const float4* yr4 = (const float4*)(Yr + row_base);
    const float4* yi4 = (const float4*)(Yi + row_base);
    const float4* sxr4 = (const float4*)sxr;
    const float4* sxi4 = (const float4*)sxi;

    // Hoist scalar epilogue params: latency hidden under the streaming loop
    const float dw  = d3w[0];
    const float db  = d3b[0];
    const float b2v = b2[0];
    const size_t idx = (size_t)b * N_SZ + n;
    const float xpr_v = xpr[idx];
    const float xpi_v = xpi[idx];

    // ---- Main streaming loop: 4 dot products + |x|^2 sum, fully unrolled --
    float rr = 0.f, ii = 0.f, ri = 0.f, ir = 0.f, ss = 0.f;

    #pragma unroll 16
    for (int k = lid; k < N_SZ / 4; k += 32) {
        float4 a = yr4[k];
        float4 c = yi4[k];
        float4 u = sxr4[k];
        float4 v = sxi4[k];
        rr = fmaf(a.x, u.x, rr); rr = fmaf(a.y, u.y, rr);
        rr = fmaf(a.z, u.z, rr); rr = fmaf(a.w, u.w, rr);
        ii = fmaf(c.x, v.x, ii); ii = fmaf(c.y, v.y, ii);
        ii = fmaf(c.z, v.z, ii); ii = fmaf(c.w, v.w, ii);
        ri = fmaf(a.x, v.x, ri); ri = fmaf(a.y, v.y, ri);
        ri = fmaf(a.z, v.z, ri); ri = fmaf(a.w, v.w, ri);
        ir = fmaf(c.x, u.x, ir); ir = fmaf(c.y, u.y, ir);
        ir = fmaf(c.z, u.z, ir); ir = fmaf(c.w, u.w, ir);
        ss = fmaf(u.x, u.x, ss); ss = fmaf(u.y, u.y, ss);
        ss = fmaf(u.z, u.z, ss); ss = fmaf(u.w, u.w, ss);
        ss = fmaf(v.x, v.x, ss); ss = fmaf(v.y, v.y, ss);
        ss = fmaf(v.z, v.z, ss); ss = fmaf(v.w, v.w, ss);
    }

    // butterfly reduce all five accumulators -> every lane has full sums
    #pragma unroll
    for (int off = 16; off > 0; off >>= 1) {
        rr += __shfl_xor_sync(0xFFFFFFFFu, rr, off);
        ii += __shfl_xor_sync(0xFFFFFFFFu, ii, off);
        ri += __shfl_xor_sync(0xFFFFFFFFu, ri, off);
        ir += __shfl_xor_sync(0xFFFFFFFFu, ir, off);
        ss += __shfl_xor_sync(0xFFFFFFFFu, ss, off);
    }

    // ---- Epilogue (per-warp; no cross-warp communication needed) ----
    const float sc = -(LAMBDA * LAMBDA) * (1.0f - ss / (float)N_SZ);

    float x1r = fmaf(LAMBDA * (rr - ii), dw, db);
    float x1i = fmaf(LAMBDA * (ri + ir), dw, db);
    x1r = fmaf(sc, xpr_v, x1r);
    x1i = fmaf(sc, xpi_v, x1i);

    const float xabs = sqrtf(x1r * x1r + x1i * x1i);

    // MLP: 256 hidden units, 8 per lane
    float partial = 0.f;
    #pragma unroll
    for (int j = lid; j < HID; j += 32) {
        float h = fmaxf(fmaf(xabs, sw1[j], sb1[j]), 0.f);
        partial = fmaf(h, sw2[j], partial);
    }
    #pragma unroll
    for (int off = 16; off > 0; off >>= 1)
        partial += __shfl_xor_sync(0xFFFFFFFFu, partial, off);

    if (lid == 0) {
        float g = tanhf(partial + b2v);
        float q = g / fmaxf(xabs, 1e-12f);
        out[idx] = x1r * q;                          // real part
        out[(size_t)B_SZ * N_SZ + idx] = x1i * q;    // imag part
    }
}

extern "C" void kernel_launch(void* const* d_in, const int* in_sizes, int n_in,
                              void* d_out, int out_size) {
    const float* Yr  = (const float*)d_in[0];
    const float* Yi  = (const float*)d_in[1];
    const float* xr  = (const float*)d_in[2];
    const float* xi  = (const float*)d_in[3];
    const float* xpr = (const float*)d_in[4];
    const float* xpi = (const float*)d_in[5];
    const float* d3w = (const float*)d_in[6];
    const float* d3b = (const float*)d_in[7];
    const float* w1  = (const float*)d_in[8];
    const float* b1  = (const float*)d_in[9];
    const float* w2  = (const float*)d_in[10];
    const float* b2  = (const float*)d_in[11];
    float* out = (float*)d_out;

    dim3 grid(N_SZ / WARPS_PER_BLOCK, B_SZ);
    fused_kernel<<<grid, THREADS>>>(Yr, Yi, xr, xi, xpr, xpi,
                                    d3w, d3b, w1, b1, w2, b2, out);
}